// round 15
// baseline (speedup 1.0000x reference)
#include <cuda_runtime.h>
#include <cstdint>

#define Bb 512
#define Tt 50
#define Ff 2048
#define H1 1024
#define H2 1024
#define Ss 16
#define SPLITK 4   // GEMM1: 4 contiguous K-chunks of 512, ascending combine (validated)
#define KC 64      // GEMM2 sparse k-chunk

__device__ float g_rate[Bb * Ff];
__device__ float g_part1[SPLITK * Bb * H1];
__device__ float g_cur1[Bb * H1];
__device__ uint32_t g_mask[Ss * Bb * 32];    // spike bitmasks: row m=s*512+b, 32 words of k
__device__ float g_cur2[Ss * Bb * H2];

// ---------------------------------------------------------------------------
// 1) Encoder: rate[b,f] = count_t( sigmoid(x) > 0.5 ) * 0.02f.
//    Cutoff x > 2^-23; /50 is the algsimp reciprocal multiply. (Bit-exact R12.)
// ---------------------------------------------------------------------------
__global__ void rate_kernel(const float* __restrict__ x) {
    const float CUT = 1.1920928955078125e-7f;   // 2^-23
    const float INV50 = 0.02f;
    int idx = blockIdx.x * blockDim.x + threadIdx.x;
    int b  = idx >> 9;
    int f4 = idx & 511;
    const float4* p = reinterpret_cast<const float4*>(x) + (size_t)b * Tt * (Ff / 4) + f4;
    int c0 = 0, c1 = 0, c2 = 0, c3 = 0;
#pragma unroll 10
    for (int t = 0; t < Tt; t++) {
        float4 v = p[(size_t)t * (Ff / 4)];
        c0 += (v.x > CUT); c1 += (v.y > CUT); c2 += (v.z > CUT); c3 += (v.w > CUT);
    }
    float4 r;
    r.x = __fmul_rn((float)c0, INV50);
    r.y = __fmul_rn((float)c1, INV50);
    r.z = __fmul_rn((float)c2, INV50);
    r.w = __fmul_rn((float)c3, INV50);
    reinterpret_cast<float4*>(g_rate)[idx] = r;
}

// ---------------------------------------------------------------------------
// GEMM1 split-K partials (validated bit-exact; unchanged).
// ---------------------------------------------------------------------------
__global__ void __launch_bounds__(256, 2)
sgemm_nt_64_part(const float* __restrict__ A, const float* __restrict__ Bm,
                 float* __restrict__ Cpart, int K, int kLen, int N)
{
    __shared__ __align__(16) float As[8][64];
    __shared__ __align__(16) float Bs[8][64];

    const int tid  = threadIdx.x;
    const int tx   = tid & 15;
    const int ty   = tid >> 4;
    const int lrow = tid >> 2;
    const int lcol = (tid & 3) * 2;
    const int kOff = blockIdx.z * kLen;

    const float* Ap = A + (size_t)(blockIdx.y * 64 + lrow) * K + kOff + lcol;
    const float* Bp = Bm + (size_t)(blockIdx.x * 64 + lrow) * K + kOff + lcol;
    float* C = Cpart + (size_t)blockIdx.z * Bb * H1;

    float acc[4][4];
#pragma unroll
    for (int i = 0; i < 4; i++)
#pragma unroll
        for (int j = 0; j < 4; j++) acc[i][j] = 0.0f;

    float2 av = *reinterpret_cast<const float2*>(Ap);
    float2 bv = *reinterpret_cast<const float2*>(Bp);

    const int kIters = kLen / 8;
    for (int it = 0; it < kIters; ++it) {
        __syncthreads();
        As[lcol + 0][lrow] = av.x; As[lcol + 1][lrow] = av.y;
        Bs[lcol + 0][lrow] = bv.x; Bs[lcol + 1][lrow] = bv.y;
        __syncthreads();
        if (it + 1 < kIters) {
            av = *reinterpret_cast<const float2*>(Ap + (it + 1) * 8);
            bv = *reinterpret_cast<const float2*>(Bp + (it + 1) * 8);
        }
#pragma unroll
        for (int k = 0; k < 8; k++) {
            float a[4], b[4];
            *reinterpret_cast<float4*>(a) = *reinterpret_cast<const float4*>(&As[k][ty * 4]);
            *reinterpret_cast<float4*>(b) = *reinterpret_cast<const float4*>(&Bs[k][tx * 4]);
#pragma unroll
            for (int i = 0; i < 4; i++)
#pragma unroll
                for (int j = 0; j < 4; j++)
                    acc[i][j] = __fmaf_rn(a[i], b[j], acc[i][j]);
        }
    }

    const int colBase = blockIdx.x * 64 + tx * 4;
#pragma unroll
    for (int i = 0; i < 4; i++) {
        int row = blockIdx.y * 64 + ty * 4 + i;
        *reinterpret_cast<float4*>(&C[(size_t)row * N + colBase]) =
            make_float4(acc[i][0], acc[i][1], acc[i][2], acc[i][3]);
    }
}

// ---------------------------------------------------------------------------
// Split-K combine: ascending linear order, then + bias.
// ---------------------------------------------------------------------------
__global__ void combine1_kernel(const float* __restrict__ b1) {
    int idx = blockIdx.x * blockDim.x + threadIdx.x;
    const int BH = Bb * H1;
    float s = g_part1[idx];
    s = __fadd_rn(s, g_part1[idx + BH]);
    s = __fadd_rn(s, g_part1[idx + 2 * BH]);
    s = __fadd_rn(s, g_part1[idx + 3 * BH]);
    g_cur1[idx] = __fadd_rn(s, b1[idx & (H1 - 1)]);
}

// ---------------------------------------------------------------------------
// 3) Layer-1 LIF scan -> spike BITMASKS via ballot.
//    mem = sub(fma(0.9, mem, c), reset)  (bit-exact R12).
//    Warp = 32 consecutive h of one b; step-s word collected on lane s.
// ---------------------------------------------------------------------------
__global__ void scan1_kernel() {
    int idx = blockIdx.x * blockDim.x + threadIdx.x;   // over Bb*H1
    int lane = idx & 31;
    float c = g_cur1[idx];
    float mem = 0.0f;
    uint32_t mine = 0;
#pragma unroll
    for (int s = 0; s < Ss; s++) {
        float reset = (mem > 1.0f) ? 1.0f : 0.0f;
        mem = __fsub_rn(__fmaf_rn(0.9f, mem, c), reset);
        uint32_t w = __ballot_sync(0xFFFFFFFFu, mem > 1.0f);
        if (lane == s) mine = w;
    }
    if (lane < Ss) {
        int b  = idx >> 10;            // batch
        int wi = (idx >> 5) & 31;      // k-word index (h0/32)
        g_mask[((size_t)lane * Bb + b) * 32 + wi] = mine;   // row m = s*512+b
    }
}

// ---------------------------------------------------------------------------
// GEMM2 SPARSE: cur2[m,n] = (ordered ascending-k sum of W2[n,k] over active k)
//               + b2[n].  Skipping a_k=0 terms is bit-identical to the dense
//               fma chain (fma(0,w,acc)=acc; fma(1,w,acc)=fadd(acc,w)).
// Tile 128m x 128n, 8 warps; warp = 16 rows x 128 cols (lane = 4 cols).
// Per active bit: 1 LDS.128 + 4 FADD; masks warp-uniform -> no divergence.
// ---------------------------------------------------------------------------
__global__ void __launch_bounds__(256, 2)
gemm2_sparse(const float* __restrict__ W2, const float* __restrict__ b2,
             float* __restrict__ C)
{
    __shared__ __align__(16) float Bs[KC][132];   // [k][n], padded
    __shared__ uint32_t Ms[128][2];               // per-row masks for this chunk

    const int tid  = threadIdx.x;
    const int lane = tid & 31;
    const int wid  = tid >> 5;
    const int m0   = blockIdx.y * 128;
    const int n0   = blockIdx.x * 128;
    const int nl   = lane * 4;               // local col base

    float4 acc[16];
#pragma unroll
    for (int r = 0; r < 16; r++) acc[r] = make_float4(0.f, 0.f, 0.f, 0.f);

    for (int ck = 0; ck < H1 / KC; ck++) {
        __syncthreads();
        // Fill Bs (transposed): W2[n][k] -> Bs[k][n]
#pragma unroll
        for (int it = 0; it < 8; it++) {
            int idx4 = it * 256 + tid;       // 0..2047
            int n  = idx4 >> 4;              // 0..127
            int kq = idx4 & 15;              // 0..15 (x4 k)
            float4 v = *reinterpret_cast<const float4*>(
                &W2[(size_t)(n0 + n) * H1 + ck * KC + kq * 4]);
            Bs[kq * 4 + 0][n] = v.x;
            Bs[kq * 4 + 1][n] = v.y;
            Bs[kq * 4 + 2][n] = v.z;
            Bs[kq * 4 + 3][n] = v.w;
        }
        // Masks: 128 rows x 2 words
        {
            int r = tid >> 1, seg = tid & 1;
            Ms[r][seg] = g_mask[(size_t)(m0 + r) * 32 + ck * 2 + seg];
        }
        __syncthreads();

#pragma unroll
        for (int r = 0; r < 16; r++) {
#pragma unroll
            for (int seg = 0; seg < 2; seg++) {
                uint32_t mask = Ms[wid * 16 + r][seg];   // warp-uniform
                while (mask) {
                    int k = __ffs(mask) - 1;
                    mask &= mask - 1;
                    float4 w = *reinterpret_cast<const float4*>(&Bs[seg * 32 + k][nl]);
                    acc[r].x = __fadd_rn(acc[r].x, w.x);
                    acc[r].y = __fadd_rn(acc[r].y, w.y);
                    acc[r].z = __fadd_rn(acc[r].z, w.z);
                    acc[r].w = __fadd_rn(acc[r].w, w.w);
                }
            }
        }
    }

    // Epilogue: + b2 (separate fp32 add, validated semantics)
    float4 bb = *reinterpret_cast<const float4*>(&b2[n0 + nl]);
#pragma unroll
    for (int r = 0; r < 16; r++) {
        int m = m0 + wid * 16 + r;
        float4 o;
        o.x = __fadd_rn(acc[r].x, bb.x);
        o.y = __fadd_rn(acc[r].y, bb.y);
        o.z = __fadd_rn(acc[r].z, bb.z);
        o.w = __fadd_rn(acc[r].w, bb.w);
        *reinterpret_cast<float4*>(&C[(size_t)m * H2 + n0 + nl]) = o;
    }
}

// ---------------------------------------------------------------------------
// 5) Layer-2 LIF scan -> final spikes.
// ---------------------------------------------------------------------------
__global__ void scan2_kernel(float* __restrict__ out) {
    int idx = blockIdx.x * blockDim.x + threadIdx.x;
    const int BH = Bb * H2;
    float mem = 0.0f;
#pragma unroll
    for (int s = 0; s < Ss; s++) {
        float c = g_cur2[s * BH + idx];
        float reset = (mem > 1.0f) ? 1.0f : 0.0f;
        mem = __fsub_rn(__fmaf_rn(0.9f, mem, c), reset);
        out[s * BH + idx] = (mem > 1.0f) ? 1.0f : 0.0f;
    }
}

// ---------------------------------------------------------------------------
extern "C" void kernel_launch(void* const* d_in, const int* in_sizes, int n_in,
                              void* d_out, int out_size)
{
    const float* x  = (const float*)d_in[0];
    const float* W1 = (const float*)d_in[1];
    const float* b1 = (const float*)d_in[2];
    const float* W2 = (const float*)d_in[3];
    const float* b2 = (const float*)d_in[4];
    float* out = (float*)d_out;

    float *rate, *part1, *cur2;
    cudaGetSymbolAddress((void**)&rate,  g_rate);
    cudaGetSymbolAddress((void**)&part1, g_part1);
    cudaGetSymbolAddress((void**)&cur2,  g_cur2);

    rate_kernel<<<(Bb * Ff / 4) / 256, 256>>>(x);

    {   // GEMM1: 4 split-K slices of 512, ascending combine + b1
        dim3 grid(H1 / 64, Bb / 64, SPLITK);
        sgemm_nt_64_part<<<grid, 256>>>(rate, W1, part1, Ff, Ff / SPLITK, H1);
    }
    combine1_kernel<<<(Bb * H1) / 256, 256>>>(b1);

    scan1_kernel<<<(Bb * H1) / 256, 256>>>();

    {   // GEMM2: sparse exact (skip zero spikes), 512 CTAs
        dim3 grid(H2 / 128, (Ss * Bb) / 128);
        gemm2_sparse<<<grid, 256>>>(W2, b2, cur2);
    }

    scan2_kernel<<<(Bb * H2) / 256, 256>>>(out);
}

// round 16
// speedup vs baseline: 1.0668x; 1.0668x over previous
#include <cuda_runtime.h>
#include <cstdint>

#define Bb 512
#define Tt 50
#define Ff 2048
#define H1 1024
#define H2 1024
#define Ss 16
#define SPLITK 4   // GEMM1: 4 contiguous K-chunks of 512, ascending combine (validated)
#define KC 64      // GEMM2 sparse k-chunk

__device__ float g_rate[Bb * Ff];
__device__ float g_part1[SPLITK * Bb * H1];
__device__ float g_cur1[Bb * H1];
__device__ uint32_t g_mask[Ss * Bb * 32];    // spike bitmasks: row m=s*512+b, 32 words of k
__device__ float g_cur2[Ss * Bb * H2];

// ---------------------------------------------------------------------------
// 1) Encoder: rate[b,f] = count_t( sigmoid(x) > 0.5 ) * 0.02f.
//    Cutoff x > 2^-23; /50 is the algsimp reciprocal multiply. (Bit-exact R12.)
// ---------------------------------------------------------------------------
__global__ void rate_kernel(const float* __restrict__ x) {
    const float CUT = 1.1920928955078125e-7f;   // 2^-23
    const float INV50 = 0.02f;
    int idx = blockIdx.x * blockDim.x + threadIdx.x;
    int b  = idx >> 9;
    int f4 = idx & 511;
    const float4* p = reinterpret_cast<const float4*>(x) + (size_t)b * Tt * (Ff / 4) + f4;
    int c0 = 0, c1 = 0, c2 = 0, c3 = 0;
#pragma unroll 10
    for (int t = 0; t < Tt; t++) {
        float4 v = p[(size_t)t * (Ff / 4)];
        c0 += (v.x > CUT); c1 += (v.y > CUT); c2 += (v.z > CUT); c3 += (v.w > CUT);
    }
    float4 r;
    r.x = __fmul_rn((float)c0, INV50);
    r.y = __fmul_rn((float)c1, INV50);
    r.z = __fmul_rn((float)c2, INV50);
    r.w = __fmul_rn((float)c3, INV50);
    reinterpret_cast<float4*>(g_rate)[idx] = r;
}

// ---------------------------------------------------------------------------
// GEMM1 split-K partials (validated bit-exact; unchanged).
// ---------------------------------------------------------------------------
__global__ void __launch_bounds__(256, 2)
sgemm_nt_64_part(const float* __restrict__ A, const float* __restrict__ Bm,
                 float* __restrict__ Cpart, int K, int kLen, int N)
{
    __shared__ __align__(16) float As[8][64];
    __shared__ __align__(16) float Bs[8][64];

    const int tid  = threadIdx.x;
    const int tx   = tid & 15;
    const int ty   = tid >> 4;
    const int lrow = tid >> 2;
    const int lcol = (tid & 3) * 2;
    const int kOff = blockIdx.z * kLen;

    const float* Ap = A + (size_t)(blockIdx.y * 64 + lrow) * K + kOff + lcol;
    const float* Bp = Bm + (size_t)(blockIdx.x * 64 + lrow) * K + kOff + lcol;
    float* C = Cpart + (size_t)blockIdx.z * Bb * H1;

    float acc[4][4];
#pragma unroll
    for (int i = 0; i < 4; i++)
#pragma unroll
        for (int j = 0; j < 4; j++) acc[i][j] = 0.0f;

    float2 av = *reinterpret_cast<const float2*>(Ap);
    float2 bv = *reinterpret_cast<const float2*>(Bp);

    const int kIters = kLen / 8;
    for (int it = 0; it < kIters; ++it) {
        __syncthreads();
        As[lcol + 0][lrow] = av.x; As[lcol + 1][lrow] = av.y;
        Bs[lcol + 0][lrow] = bv.x; Bs[lcol + 1][lrow] = bv.y;
        __syncthreads();
        if (it + 1 < kIters) {
            av = *reinterpret_cast<const float2*>(Ap + (it + 1) * 8);
            bv = *reinterpret_cast<const float2*>(Bp + (it + 1) * 8);
        }
#pragma unroll
        for (int k = 0; k < 8; k++) {
            float a[4], b[4];
            *reinterpret_cast<float4*>(a) = *reinterpret_cast<const float4*>(&As[k][ty * 4]);
            *reinterpret_cast<float4*>(b) = *reinterpret_cast<const float4*>(&Bs[k][tx * 4]);
#pragma unroll
            for (int i = 0; i < 4; i++)
#pragma unroll
                for (int j = 0; j < 4; j++)
                    acc[i][j] = __fmaf_rn(a[i], b[j], acc[i][j]);
        }
    }

    const int colBase = blockIdx.x * 64 + tx * 4;
#pragma unroll
    for (int i = 0; i < 4; i++) {
        int row = blockIdx.y * 64 + ty * 4 + i;
        *reinterpret_cast<float4*>(&C[(size_t)row * N + colBase]) =
            make_float4(acc[i][0], acc[i][1], acc[i][2], acc[i][3]);
    }
}

// ---------------------------------------------------------------------------
// Split-K combine: ascending linear order, then + bias.
// ---------------------------------------------------------------------------
__global__ void combine1_kernel(const float* __restrict__ b1) {
    int idx = blockIdx.x * blockDim.x + threadIdx.x;
    const int BH = Bb * H1;
    float s = g_part1[idx];
    s = __fadd_rn(s, g_part1[idx + BH]);
    s = __fadd_rn(s, g_part1[idx + 2 * BH]);
    s = __fadd_rn(s, g_part1[idx + 3 * BH]);
    g_cur1[idx] = __fadd_rn(s, b1[idx & (H1 - 1)]);
}

// ---------------------------------------------------------------------------
// 3) Layer-1 LIF scan -> spike BITMASKS via ballot (validated R15).
// ---------------------------------------------------------------------------
__global__ void scan1_kernel() {
    int idx = blockIdx.x * blockDim.x + threadIdx.x;   // over Bb*H1
    int lane = idx & 31;
    float c = g_cur1[idx];
    float mem = 0.0f;
    uint32_t mine = 0;
#pragma unroll
    for (int s = 0; s < Ss; s++) {
        float reset = (mem > 1.0f) ? 1.0f : 0.0f;
        mem = __fsub_rn(__fmaf_rn(0.9f, mem, c), reset);
        uint32_t w = __ballot_sync(0xFFFFFFFFu, mem > 1.0f);
        if (lane == s) mine = w;
    }
    if (lane < Ss) {
        int b  = idx >> 10;            // batch
        int wi = (idx >> 5) & 31;      // k-word index (h0/32)
        g_mask[((size_t)lane * Bb + b) * 32 + wi] = mine;   // row m = s*512+b
    }
}

// ---------------------------------------------------------------------------
// GEMM2 SPARSE v2: per-chunk ascending index lists + x4-unrolled walk.
// cur2[m,n] = ordered ascending-k sum of W2[n,k] over active k, + b2[n].
// Bit-identical to the dense fma chain (fma(0,w,acc)=acc; fma(1,w,acc)=
// fadd(acc,w); pad index 64 hits an all-zero row: fadd(acc,+0)=acc).
// Tile 128m x 128n, 8 warps; warp = 16 rows x 128 cols (lane = 4 cols).
// ---------------------------------------------------------------------------
__global__ void __launch_bounds__(256, 2)
gemm2_sparse(const float* __restrict__ W2, const float* __restrict__ b2,
             float* __restrict__ C)
{
    __shared__ __align__(16) float Bs[KC + 1][132];  // row KC = zeros (padding target)
    __shared__ uint32_t Ms[128][2];                  // per-row masks for this chunk
    __shared__ __align__(4) uint8_t Ls[128][72];     // per-row ascending k-lists (padded)
    __shared__ int Cnt[128];                         // padded counts (multiple of 4)

    const int tid  = threadIdx.x;
    const int lane = tid & 31;
    const int wid  = tid >> 5;
    const int m0   = blockIdx.y * 128;
    const int n0   = blockIdx.x * 128;
    const int nl   = lane * 4;               // local col base

    // zero padding row (never overwritten afterwards)
    for (int i = tid; i < 132; i += 256) Bs[KC][i] = 0.0f;

    float4 acc[16];
#pragma unroll
    for (int r = 0; r < 16; r++) acc[r] = make_float4(0.f, 0.f, 0.f, 0.f);

    for (int ck = 0; ck < H1 / KC; ck++) {
        __syncthreads();
        // Fill Bs (transposed): W2[n][k] -> Bs[k][n]
#pragma unroll
        for (int it = 0; it < 8; it++) {
            int idx4 = it * 256 + tid;       // 0..2047
            int n  = idx4 >> 4;              // 0..127
            int kq = idx4 & 15;              // 0..15 (x4 k)
            float4 v = *reinterpret_cast<const float4*>(
                &W2[(size_t)(n0 + n) * H1 + ck * KC + kq * 4]);
            Bs[kq * 4 + 0][n] = v.x;
            Bs[kq * 4 + 1][n] = v.y;
            Bs[kq * 4 + 2][n] = v.z;
            Bs[kq * 4 + 3][n] = v.w;
        }
        // Masks: 128 rows x 2 words
        {
            int r = tid >> 1, seg = tid & 1;
            Ms[r][seg] = g_mask[(size_t)(m0 + r) * 32 + ck * 2 + seg];
        }
        __syncthreads();

        // Build ascending index lists (one thread per row), pad to x4 with KC
        if (tid < 128) {
            uint32_t w0 = Ms[tid][0], w1 = Ms[tid][1];
            int c = 0;
            while (w0) { int k = __ffs(w0) - 1; w0 &= w0 - 1; Ls[tid][c++] = (uint8_t)k; }
            while (w1) { int k = __ffs(w1) - 1; w1 &= w1 - 1; Ls[tid][c++] = (uint8_t)(k + 32); }
            int cp = (c + 3) & ~3;
            while (c < cp) Ls[tid][c++] = (uint8_t)KC;
            Cnt[tid] = cp;
        }
        __syncthreads();

#pragma unroll
        for (int r = 0; r < 16; r++) {
            const int row = wid * 16 + r;
            const int cnt = Cnt[row];                        // broadcast
            const uint8_t* lp = &Ls[row][0];
            for (int i = 0; i < cnt; i += 4) {
                uint32_t q = *reinterpret_cast<const uint32_t*>(lp + i);  // broadcast
                int k0 = q & 255, k1 = (q >> 8) & 255, k2 = (q >> 16) & 255, k3 = q >> 24;
                float4 w0v = *reinterpret_cast<const float4*>(&Bs[k0][nl]);
                float4 w1v = *reinterpret_cast<const float4*>(&Bs[k1][nl]);
                float4 w2v = *reinterpret_cast<const float4*>(&Bs[k2][nl]);
                float4 w3v = *reinterpret_cast<const float4*>(&Bs[k3][nl]);
                // ascending chain k0 -> k1 -> k2 -> k3 (4-way ILP across components)
                acc[r].x = __fadd_rn(__fadd_rn(__fadd_rn(__fadd_rn(acc[r].x, w0v.x), w1v.x), w2v.x), w3v.x);
                acc[r].y = __fadd_rn(__fadd_rn(__fadd_rn(__fadd_rn(acc[r].y, w0v.y), w1v.y), w2v.y), w3v.y);
                acc[r].z = __fadd_rn(__fadd_rn(__fadd_rn(__fadd_rn(acc[r].z, w0v.z), w1v.z), w2v.z), w3v.z);
                acc[r].w = __fadd_rn(__fadd_rn(__fadd_rn(__fadd_rn(acc[r].w, w0v.w), w1v.w), w2v.w), w3v.w);
            }
        }
    }

    // Epilogue: + b2 (separate fp32 add, validated semantics)
    float4 bb = *reinterpret_cast<const float4*>(&b2[n0 + nl]);
#pragma unroll
    for (int r = 0; r < 16; r++) {
        int m = m0 + wid * 16 + r;
        float4 o;
        o.x = __fadd_rn(acc[r].x, bb.x);
        o.y = __fadd_rn(acc[r].y, bb.y);
        o.z = __fadd_rn(acc[r].z, bb.z);
        o.w = __fadd_rn(acc[r].w, bb.w);
        *reinterpret_cast<float4*>(&C[(size_t)m * H2 + n0 + nl]) = o;
    }
}

// ---------------------------------------------------------------------------
// 5) Layer-2 LIF scan -> final spikes.
// ---------------------------------------------------------------------------
__global__ void scan2_kernel(float* __restrict__ out) {
    int idx = blockIdx.x * blockDim.x + threadIdx.x;
    const int BH = Bb * H2;
    float mem = 0.0f;
#pragma unroll
    for (int s = 0; s < Ss; s++) {
        float c = g_cur2[s * BH + idx];
        float reset = (mem > 1.0f) ? 1.0f : 0.0f;
        mem = __fsub_rn(__fmaf_rn(0.9f, mem, c), reset);
        out[s * BH + idx] = (mem > 1.0f) ? 1.0f : 0.0f;
    }
}

// ---------------------------------------------------------------------------
extern "C" void kernel_launch(void* const* d_in, const int* in_sizes, int n_in,
                              void* d_out, int out_size)
{
    const float* x  = (const float*)d_in[0];
    const float* W1 = (const float*)d_in[1];
    const float* b1 = (const float*)d_in[2];
    const float* W2 = (const float*)d_in[3];
    const float* b2 = (const float*)d_in[4];
    float* out = (float*)d_out;

    float *rate, *part1, *cur2;
    cudaGetSymbolAddress((void**)&rate,  g_rate);
    cudaGetSymbolAddress((void**)&part1, g_part1);
    cudaGetSymbolAddress((void**)&cur2,  g_cur2);

    rate_kernel<<<(Bb * Ff / 4) / 256, 256>>>(x);

    {   // GEMM1: 4 split-K slices of 512, ascending combine + b1
        dim3 grid(H1 / 64, Bb / 64, SPLITK);
        sgemm_nt_64_part<<<grid, 256>>>(rate, W1, part1, Ff, Ff / SPLITK, H1);
    }
    combine1_kernel<<<(Bb * H1) / 256, 256>>>(b1);

    scan1_kernel<<<(Bb * H1) / 256, 256>>>();

    {   // GEMM2: sparse exact v2 (index lists, x4 unroll), 512 CTAs
        dim3 grid(H2 / 128, (Ss * Bb) / 128);
        gemm2_sparse<<<grid, 256>>>(W2, b2, cur2);
    }

    scan2_kernel<<<(Bb * H2) / 256, 256>>>(out);
}

// round 17
// speedup vs baseline: 1.1332x; 1.0622x over previous
#include <cuda_runtime.h>
#include <cstdint>

#define Bb 512
#define Tt 50
#define Ff 2048
#define H1 1024
#define H2 1024
#define Ss 16
#define SPLITK 4   // GEMM1: 4 contiguous K-chunks of 512, ascending combine (validated)

__device__ float g_rate[Bb * Ff];
__device__ float g_part1[SPLITK * Bb * H1];
__device__ float g_cur1[Bb * H1];
__device__ uint16_t g_pat[Bb * H1];     // 16-bit temporal spike pattern per (b,h)
__device__ float g_w2t[H1 * H2];        // W2 transposed: W2T[h][n]
__device__ float g_cur2[Ss * Bb * H2];

// ---------------------------------------------------------------------------
// 1) Encoder: rate[b,f] = count_t( sigmoid(x) > 0.5 ) * 0.02f.
//    Cutoff x > 2^-23; /50 is the algsimp reciprocal multiply. (Bit-exact R12.)
// ---------------------------------------------------------------------------
__global__ void rate_kernel(const float* __restrict__ x) {
    const float CUT = 1.1920928955078125e-7f;   // 2^-23
    const float INV50 = 0.02f;
    int idx = blockIdx.x * blockDim.x + threadIdx.x;
    int b  = idx >> 9;
    int f4 = idx & 511;
    const float4* p = reinterpret_cast<const float4*>(x) + (size_t)b * Tt * (Ff / 4) + f4;
    int c0 = 0, c1 = 0, c2 = 0, c3 = 0;
#pragma unroll 10
    for (int t = 0; t < Tt; t++) {
        float4 v = p[(size_t)t * (Ff / 4)];
        c0 += (v.x > CUT); c1 += (v.y > CUT); c2 += (v.z > CUT); c3 += (v.w > CUT);
    }
    float4 r;
    r.x = __fmul_rn((float)c0, INV50);
    r.y = __fmul_rn((float)c1, INV50);
    r.z = __fmul_rn((float)c2, INV50);
    r.w = __fmul_rn((float)c3, INV50);
    reinterpret_cast<float4*>(g_rate)[idx] = r;
}

// ---------------------------------------------------------------------------
// GEMM1 split-K partials (validated bit-exact; unchanged).
// ---------------------------------------------------------------------------
__global__ void __launch_bounds__(256, 2)
sgemm_nt_64_part(const float* __restrict__ A, const float* __restrict__ Bm,
                 float* __restrict__ Cpart, int K, int kLen, int N)
{
    __shared__ __align__(16) float As[8][64];
    __shared__ __align__(16) float Bs[8][64];

    const int tid  = threadIdx.x;
    const int tx   = tid & 15;
    const int ty   = tid >> 4;
    const int lrow = tid >> 2;
    const int lcol = (tid & 3) * 2;
    const int kOff = blockIdx.z * kLen;

    const float* Ap = A + (size_t)(blockIdx.y * 64 + lrow) * K + kOff + lcol;
    const float* Bp = Bm + (size_t)(blockIdx.x * 64 + lrow) * K + kOff + lcol;
    float* C = Cpart + (size_t)blockIdx.z * Bb * H1;

    float acc[4][4];
#pragma unroll
    for (int i = 0; i < 4; i++)
#pragma unroll
        for (int j = 0; j < 4; j++) acc[i][j] = 0.0f;

    float2 av = *reinterpret_cast<const float2*>(Ap);
    float2 bv = *reinterpret_cast<const float2*>(Bp);

    const int kIters = kLen / 8;
    for (int it = 0; it < kIters; ++it) {
        __syncthreads();
        As[lcol + 0][lrow] = av.x; As[lcol + 1][lrow] = av.y;
        Bs[lcol + 0][lrow] = bv.x; Bs[lcol + 1][lrow] = bv.y;
        __syncthreads();
        if (it + 1 < kIters) {
            av = *reinterpret_cast<const float2*>(Ap + (it + 1) * 8);
            bv = *reinterpret_cast<const float2*>(Bp + (it + 1) * 8);
        }
#pragma unroll
        for (int k = 0; k < 8; k++) {
            float a[4], b[4];
            *reinterpret_cast<float4*>(a) = *reinterpret_cast<const float4*>(&As[k][ty * 4]);
            *reinterpret_cast<float4*>(b) = *reinterpret_cast<const float4*>(&Bs[k][tx * 4]);
#pragma unroll
            for (int i = 0; i < 4; i++)
#pragma unroll
                for (int j = 0; j < 4; j++)
                    acc[i][j] = __fmaf_rn(a[i], b[j], acc[i][j]);
        }
    }

    const int colBase = blockIdx.x * 64 + tx * 4;
#pragma unroll
    for (int i = 0; i < 4; i++) {
        int row = blockIdx.y * 64 + ty * 4 + i;
        *reinterpret_cast<float4*>(&C[(size_t)row * N + colBase]) =
            make_float4(acc[i][0], acc[i][1], acc[i][2], acc[i][3]);
    }
}

// ---------------------------------------------------------------------------
// Split-K combine: ascending linear order, then + bias.
// ---------------------------------------------------------------------------
__global__ void combine1_kernel(const float* __restrict__ b1) {
    int idx = blockIdx.x * blockDim.x + threadIdx.x;
    const int BH = Bb * H1;
    float s = g_part1[idx];
    s = __fadd_rn(s, g_part1[idx + BH]);
    s = __fadd_rn(s, g_part1[idx + 2 * BH]);
    s = __fadd_rn(s, g_part1[idx + 3 * BH]);
    g_cur1[idx] = __fadd_rn(s, b1[idx & (H1 - 1)]);
}

// ---------------------------------------------------------------------------
// W2 transpose: W2T[h][n] = W2[n][h]  (one-time, 4 MB).
// ---------------------------------------------------------------------------
__global__ void transpose_w2(const float* __restrict__ W2) {
    __shared__ float t[32][33];
    int hb = blockIdx.x * 32, nb = blockIdx.y * 32;
#pragma unroll
    for (int i = threadIdx.y; i < 32; i += 8)
        t[i][threadIdx.x] = W2[(size_t)(nb + i) * H1 + hb + threadIdx.x];
    __syncthreads();
#pragma unroll
    for (int i = threadIdx.y; i < 32; i += 8)
        g_w2t[(size_t)(hb + i) * H2 + nb + threadIdx.x] = t[threadIdx.x][i];
}

// ---------------------------------------------------------------------------
// 3) Layer-1 LIF scan -> 16-bit temporal pattern per neuron (no ballot).
//    mem = sub(fma(0.9, mem, c), reset)   (bit-exact R12)
// ---------------------------------------------------------------------------
__global__ void scan1_kernel() {
    int idx = blockIdx.x * blockDim.x + threadIdx.x;   // b*H1 + h
    float c = g_cur1[idx];
    float mem = 0.0f;
    uint32_t pat = 0;
#pragma unroll
    for (int s = 0; s < Ss; s++) {
        float reset = (mem > 1.0f) ? 1.0f : 0.0f;
        mem = __fsub_rn(__fmaf_rn(0.9f, mem, c), reset);
        pat |= ((mem > 1.0f) ? 1u : 0u) << s;
    }
    g_pat[idx] = (uint16_t)pat;
}

// ---------------------------------------------------------------------------
// GEMM2 pattern-sparse: CTA = one batch row b; 8 warps x 128 n-cols.
// For h ascending: skip neurons that never fire (warp-uniform branch);
// otherwise one LDG.128 of W2T[h] feeds all 16 step-accumulators via
// statically predicated adds. Executed FADDs per output = ascending-h chain
// == dense fma chain bit-for-bit (fma(0,w,acc)=acc; fma(1,w,acc)=fadd).
// ---------------------------------------------------------------------------
__global__ void __launch_bounds__(256, 2)
gemm2_pat(const float* __restrict__ b2, float* __restrict__ C)
{
    __shared__ uint16_t pat[H1];

    const int tid  = threadIdx.x;
    const int lane = tid & 31;
    const int wid  = tid >> 5;
    const int b    = blockIdx.x;
    const int n0   = wid * 128 + lane * 4;

    // stage patterns for this b (256 threads x 4 u16 = one u64 each)
    reinterpret_cast<uint64_t*>(pat)[tid] =
        reinterpret_cast<const uint64_t*>(g_pat)[(size_t)b * (H1 / 4) + tid];
    __syncthreads();

    float4 acc[Ss];
#pragma unroll
    for (int s = 0; s < Ss; s++) acc[s] = make_float4(0.f, 0.f, 0.f, 0.f);

    const float* Wt = g_w2t + n0;
    for (int h = 0; h < H1; h++) {
        uint32_t p = pat[h];                  // warp-uniform broadcast
        if (p) {
            float4 w = *reinterpret_cast<const float4*>(&Wt[(size_t)h * H2]);
#pragma unroll
            for (int s = 0; s < Ss; s++) {
                if ((p >> s) & 1u) {
                    acc[s].x = __fadd_rn(acc[s].x, w.x);
                    acc[s].y = __fadd_rn(acc[s].y, w.y);
                    acc[s].z = __fadd_rn(acc[s].z, w.z);
                    acc[s].w = __fadd_rn(acc[s].w, w.w);
                }
            }
        }
    }

    // Epilogue: + b2 (separate fp32 add, validated semantics)
    float4 bb = *reinterpret_cast<const float4*>(&b2[n0]);
#pragma unroll
    for (int s = 0; s < Ss; s++) {
        float4 o;
        o.x = __fadd_rn(acc[s].x, bb.x);
        o.y = __fadd_rn(acc[s].y, bb.y);
        o.z = __fadd_rn(acc[s].z, bb.z);
        o.w = __fadd_rn(acc[s].w, bb.w);
        *reinterpret_cast<float4*>(&C[((size_t)s * Bb + b) * H2 + n0]) = o;
    }
}

// ---------------------------------------------------------------------------
// 5) Layer-2 LIF scan -> final spikes.
// ---------------------------------------------------------------------------
__global__ void scan2_kernel(float* __restrict__ out) {
    int idx = blockIdx.x * blockDim.x + threadIdx.x;
    const int BH = Bb * H2;
    float mem = 0.0f;
#pragma unroll
    for (int s = 0; s < Ss; s++) {
        float c = g_cur2[s * BH + idx];
        float reset = (mem > 1.0f) ? 1.0f : 0.0f;
        mem = __fsub_rn(__fmaf_rn(0.9f, mem, c), reset);
        out[s * BH + idx] = (mem > 1.0f) ? 1.0f : 0.0f;
    }
}

// ---------------------------------------------------------------------------
extern "C" void kernel_launch(void* const* d_in, const int* in_sizes, int n_in,
                              void* d_out, int out_size)
{
    const float* x  = (const float*)d_in[0];
    const float* W1 = (const float*)d_in[1];
    const float* b1 = (const float*)d_in[2];
    const float* W2 = (const float*)d_in[3];
    const float* b2 = (const float*)d_in[4];
    float* out = (float*)d_out;

    float *rate, *part1, *cur2;
    cudaGetSymbolAddress((void**)&rate,  g_rate);
    cudaGetSymbolAddress((void**)&part1, g_part1);
    cudaGetSymbolAddress((void**)&cur2,  g_cur2);

    rate_kernel<<<(Bb * Ff / 4) / 256, 256>>>(x);

    {   // W2 transpose (runs concurrently with GEMM1 chain)
        dim3 grid(H1 / 32, H2 / 32);
        transpose_w2<<<grid, dim3(32, 8)>>>(W2);
    }

    {   // GEMM1: 4 split-K slices of 512, ascending combine + b1
        dim3 grid(H1 / 64, Bb / 64, SPLITK);
        sgemm_nt_64_part<<<grid, 256>>>(rate, W1, part1, Ff, Ff / SPLITK, H1);
    }
    combine1_kernel<<<(Bb * H1) / 256, 256>>>(b1);

    scan1_kernel<<<(Bb * H1) / 256, 256>>>();

    // GEMM2: pattern-sparse, one CTA per batch row
    gemm2_pat<<<Bb, 256>>>(b2, cur2);

    scan2_kernel<<<(Bb * H2) / 256, 256>>>(out);
}